// round 16
// baseline (speedup 1.0000x reference)
#include <cuda_runtime.h>

#define NR 512
#define DD 768
#define EPSF 1e-8f
#define LN2F 0.69314718055994530942f
#define LAMBDF 1.0f

#define TI 16                // pair tile is 16x16
#define BK 64                // k-chunk; 12 chunks; double-buffered smem ~17.4KB
#define BK4 (BK/4)           // 16 float4 per row-chunk
#define PADF 68              // 64 + 4 floats: stride 17 float4 (odd) -> conflict-free LDS.128
#define PAD4 (PADF/4)        // 17
#define NKB (DD/BK)          // 12
#define NBLK ((NR/TI)*(NR/TI))   // 1024 pair blocks
#define NT 128               // 4 warps -> all 4 SMSPs

typedef unsigned long long ull;

// Raw MUFU.LG2/EX2, ftz (exact for our range s in [2e-8, 2]).
__device__ __forceinline__ float flg2(float x) {
    float r;
    asm("lg2.approx.ftz.f32 %0, %1;" : "=f"(r) : "f"(x));
    return r;
}
__device__ __forceinline__ float fex2(float x) {
    float r;
    asm("ex2.approx.ftz.f32 %0, %1;" : "=f"(r) : "f"(x));
    return r;
}
__device__ __forceinline__ void cp16(unsigned dst, const void* src) {
    asm volatile("cp.async.cg.shared.global [%0], [%1], 16;" :: "r"(dst), "l"(src));
}

// Packed f32x2 helpers (Blackwell FFMA2 path — ptxas never auto-emits these).
__device__ __forceinline__ ull pk2(float lo, float hi) {
    ull r;
    asm("mov.b64 %0, {%1, %2};" : "=l"(r) : "f"(lo), "f"(hi));
    return r;
}
__device__ __forceinline__ void upk2(ull v, float& lo, float& hi) {
    asm("mov.b64 {%0, %1}, %2;" : "=f"(lo), "=f"(hi) : "l"(v));
}
__device__ __forceinline__ ull fma2(ull a, ull b, ull c) {
    ull r;
    asm("fma.rn.f32x2 %0, %1, %2, %3;" : "=l"(r) : "l"(a), "l"(b), "l"(c));
    return r;
}

// Packed pair of polynomial log2 on the FMA pipe.
// m = mantissa in [1,2); r = m*(2/3) - 1 in [-1/3, 1/3); exact Taylor deg-8 of
// lg2(1.5*(1+r)) recentered: u = (eb - 126.4150375) + r*q(r). |err| <= 8.1e-6.
__device__ __forceinline__ ull plg2x2(float s0, float s1) {
    int v0 = __float_as_int(s0), v1 = __float_as_int(s1);
    float m0 = __int_as_float((v0 & 0x007FFFFF) | 0x3F800000);
    float m1 = __int_as_float((v1 & 0x007FFFFF) | 0x3F800000);
    float r0 = fmaf(m0, 0.66666669f, -1.0f);
    float r1 = fmaf(m1, 0.66666669f, -1.0f);
    float b0 = (float)(v0 >> 23) - 126.41503750f;   // eb-127+lg2(1.5)
    float b1 = (float)(v1 >> 23) - 126.41503750f;
    ull R = pk2(r0, r1);
    ull q = pk2(-0.18033688f, -0.18033688f);
    q = fma2(q, R, pk2( 0.20609929f,  0.20609929f));
    q = fma2(q, R, pk2(-0.24044917f, -0.24044917f));
    q = fma2(q, R, pk2( 0.28853901f,  0.28853901f));
    q = fma2(q, R, pk2(-0.36067376f, -0.36067376f));
    q = fma2(q, R, pk2( 0.48089835f,  0.48089835f));
    q = fma2(q, R, pk2(-0.72134752f, -0.72134752f));
    q = fma2(q, R, pk2( 1.44269504f,  1.44269504f));
    return fma2(R, q, pk2(b0, b1));
}

// Scratch (no cudaMalloc allowed)
__device__ float    g_P1[NR * DD];   // p1 + eps
__device__ float    g_P2[NR * DD];   // p2 + eps
__device__ float    g_H1[NR];        // sum p1*ln(p1+eps)
__device__ float    g_H2[NR];
__device__ float    g_ptot[NBLK];    // per-block tot partials
__device__ float    g_pdia[NBLK];    // per-block dia partials
__device__ unsigned g_counter = 0;   // ticket for last-block finalize (self-resetting)

// One block per row; blocks [0,512) -> z1, [512,1024) -> z2. 256 threads, 3 elems each.
__global__ void softmax_kernel(const float* __restrict__ z1,
                               const float* __restrict__ z2) {
    const int  row   = blockIdx.x & (NR - 1);
    const bool first = blockIdx.x < NR;
    const float* src = (first ? z1 : z2) + row * DD;
    float*       dst = (first ? g_P1 : g_P2) + row * DD;
    float*      hrow = first ? g_H1 : g_H2;

    const int tid = threadIdx.x;
    const int w = tid >> 5, l = tid & 31;

    float x0 = src[tid];
    float x1 = src[tid + 256];
    float x2 = src[tid + 512];

    __shared__ float sred[8];

    float mx = fmaxf(x0, fmaxf(x1, x2));
    #pragma unroll
    for (int o = 16; o; o >>= 1) mx = fmaxf(mx, __shfl_xor_sync(0xffffffffu, mx, o));
    if (l == 0) sred[w] = mx;
    __syncthreads();
    mx = sred[0];
    #pragma unroll
    for (int i = 1; i < 8; i++) mx = fmaxf(mx, sred[i]);
    __syncthreads();

    const float L2E = 1.4426950408889634f;
    float e0 = fex2((x0 - mx) * L2E);
    float e1 = fex2((x1 - mx) * L2E);
    float e2 = fex2((x2 - mx) * L2E);
    float s = e0 + e1 + e2;
    #pragma unroll
    for (int o = 16; o; o >>= 1) s += __shfl_xor_sync(0xffffffffu, s, o);
    if (l == 0) sred[w] = s;
    __syncthreads();
    s = sred[0];
    #pragma unroll
    for (int i = 1; i < 8; i++) s += sred[i];
    __syncthreads();

    const float inv = 1.0f / s;
    float p0 = e0 * inv, p1 = e1 * inv, p2 = e2 * inv;
    float a0 = p0 + EPSF, a1 = p1 + EPSF, a2 = p2 + EPSF;
    dst[tid]       = a0;
    dst[tid + 256] = a1;
    dst[tid + 512] = a2;

    float h = p0 * flg2(a0) + p1 * flg2(a1) + p2 * flg2(a2);
    #pragma unroll
    for (int o = 16; o; o >>= 1) h += __shfl_xor_sync(0xffffffffu, h, o);
    if (l == 0) sred[w] = h;
    __syncthreads();
    if (tid == 0) {
        float hs = 0.f;
        #pragma unroll
        for (int i = 0; i < 8; i++) hs += sred[i];
        hrow[row] = hs * LN2F;
    }
}

// 16x16 pair tile per block, 128 threads (4 warps), each thread a 2x1 micro-tile.
// cp.async double-buffered k-pipeline. Per k-iter (8 lg2): 6 via MUFU, 2 via a
// PACKED f32x2 polynomial on the FMA pipe (one Horner chain for both) — cuts
// the binding MUFU floor by 25% vs all-MUFU while keeping issue under it.
__global__ void __launch_bounds__(NT, 6) pair_kernel(float* __restrict__ out) {
    __shared__ float As[2][TI * PADF];
    __shared__ float Bs[2][TI * PADF];
    __shared__ float rt4[4], rd4[4];
    __shared__ bool  s_last;

    const int tid = threadIdx.x;
    const int ib = blockIdx.x & 31;   // 512/16 = 32 tiles per dim
    const int jb = blockIdx.x >> 5;
    const int ti = tid & 7;           // i rows: ti, ti+8
    const int tj = tid >> 3;          // j row: tj (0..15)

    const float4* gp1 = (const float4*)(g_P1 + ib * TI * DD);
    const float4* gp2 = (const float4*)(g_P2 + jb * TI * DD);

    // Per-chunk loads: 16x16=256 float4 per matrix, 128 threads -> 2 apiece
    int lrow[2], lcol[2];
    #pragma unroll
    for (int r = 0; r < 2; r++) {
        int idx = tid + r * NT;
        lrow[r] = idx >> 4;     // /16
        lcol[r] = idx & 15;
    }

    #define ISSUE_LOAD(kb, buf)                                                 \
    {                                                                           \
        _Pragma("unroll")                                                       \
        for (int r = 0; r < 2; r++) {                                           \
            int go = lrow[r] * (DD / 4) + (kb) * BK4 + lcol[r];                 \
            unsigned sa = (unsigned)__cvta_generic_to_shared(                   \
                &As[buf][lrow[r] * PADF + lcol[r] * 4]);                        \
            unsigned sb = (unsigned)__cvta_generic_to_shared(                   \
                &Bs[buf][lrow[r] * PADF + lcol[r] * 4]);                        \
            cp16(sa, gp1 + go);                                                 \
            cp16(sb, gp2 + go);                                                 \
        }                                                                       \
        asm volatile("cp.async.commit_group;");                                 \
    }

    // MUFU-path accumulators (row0: x,z -> T1e0, y -> T1o0; row1 likewise)
    float T1e0 = 0.f, T1o0 = 0.f, T1e1 = 0.f, T1o1 = 0.f;
    // Packed poly-path accumulator: lo = row0.w terms, hi = row1.w terms
    ull Tp = pk2(0.0f, 0.0f);

    ISSUE_LOAD(0, 0);

    #pragma unroll 1
    for (int kb = 0; kb < NKB; kb++) {
        const int buf = kb & 1;
        if (kb + 1 < NKB) {
            ISSUE_LOAD(kb + 1, buf ^ 1);
            asm volatile("cp.async.wait_group 1;");
        } else {
            asm volatile("cp.async.wait_group 0;");
        }
        __syncthreads();

        const float4* a0p = (const float4*)(As[buf] + ti * PADF);
        const float4* a1p = (const float4*)(As[buf] + (ti + 8) * PADF);
        const float4* bp  = (const float4*)(Bs[buf] + tj * PADF);

        #pragma unroll
        for (int k = 0; k < BK4; k++) {
            float4 a0 = a0p[k], a1 = a1p[k];
            float4 b  = bp[k];

            // x,y,z of both rows via MUFU (6 lg2)
            {
                float s0 = a0.x + b.x;  float u0 = flg2(s0);
                float s1 = a0.y + b.y;  float u1 = flg2(s1);
                float s2 = a0.z + b.z;  float u2 = flg2(s2);
                T1e0 = fmaf(s0, u0, T1e0);
                T1o0 = fmaf(s1, u1, T1o0);
                T1e0 = fmaf(s2, u2, T1e0);
            }
            {
                float s0 = a1.x + b.x;  float u0 = flg2(s0);
                float s1 = a1.y + b.y;  float u1 = flg2(s1);
                float s2 = a1.z + b.z;  float u2 = flg2(s2);
                T1e1 = fmaf(s0, u0, T1e1);
                T1o1 = fmaf(s1, u1, T1o1);
                T1e1 = fmaf(s2, u2, T1e1);
            }
            // w of both rows via packed FMA-pipe polynomial (2 lg2, 1 chain)
            {
                float s3r0 = a0.w + b.w;
                float s3r1 = a1.w + b.w;
                ull U = plg2x2(s3r0, s3r1);
                Tp = fma2(pk2(s3r0, s3r1), U, Tp);
            }
        }
        __syncthreads();   // orders last reads of buf before it is overwritten
    }
    #undef ISSUE_LOAD

    float Tp0, Tp1;
    upk2(Tp, Tp0, Tp1);

    const int gi0 = ib * TI + ti,  gi1 = gi0 + 8;
    const int gj  = jb * TI + tj;

    const float h10 = g_H1[gi0], h11 = g_H1[gi1];
    const float h2j = g_H2[gj];

    // C ~= ln2*(T1 - 2); jsd = 0.5*(H1 + H2 - C); eps correction is
    // common-mode and cancels in pos-neg (residual ~2e-8 abs).
    #define JSD(T1v, hi, hj) \
        (0.5f * ((hi) + (hj) - LN2F * ((T1v) - 2.0f)))
    float j0 = JSD((T1e0 + T1o0) + Tp0, h10, h2j);
    float j1 = JSD((T1e1 + T1o1) + Tp1, h11, h2j);
    #undef JSD

    float t = j0 + j1;
    float d = 0.f;
    if (gi0 == gj) d += j0;
    if (gi1 == gj) d += j1;

    const int w = tid >> 5, l = tid & 31;
    #pragma unroll
    for (int o = 16; o; o >>= 1) {
        t += __shfl_xor_sync(0xffffffffu, t, o);
        d += __shfl_xor_sync(0xffffffffu, d, o);
    }
    if (l == 0) { rt4[w] = t; rd4[w] = d; }
    __syncthreads();

    if (tid == 0) {
        g_ptot[blockIdx.x] = (rt4[0] + rt4[1]) + (rt4[2] + rt4[3]);
        g_pdia[blockIdx.x] = (rd4[0] + rd4[1]) + (rd4[2] + rd4[3]);
        __threadfence();
        unsigned ticket = atomicAdd(&g_counter, 1u);
        s_last = (ticket == (unsigned)(gridDim.x - 1));
    }
    __syncthreads();

    if (s_last) {
        double dt = 0.0, dd_ = 0.0;
        #pragma unroll
        for (int i = tid; i < NBLK; i += NT) {
            float pt = *(volatile float*)&g_ptot[i];
            float pd = *(volatile float*)&g_pdia[i];
            dt  += (double)pt;
            dd_ += (double)pd;
        }
        #pragma unroll
        for (int o = 16; o; o >>= 1) {
            dt  += __shfl_xor_sync(0xffffffffu, dt, o);
            dd_ += __shfl_xor_sync(0xffffffffu, dd_, o);
        }
        __shared__ double dtot[4], ddia[4];
        if (l == 0) { dtot[w] = dt; ddia[w] = dd_; }
        __syncthreads();
        if (tid == 0) {
            double tot  = (dtot[0] + dtot[1]) + (dtot[2] + dtot[3]);
            double dia_ = (ddia[0] + ddia[1]) + (ddia[2] + ddia[3]);
            double pos = dia_ / (double)NR;
            double neg = -(tot - dia_) / ((double)NR * NR - NR);
            out[0] = (float)(pos + (double)LAMBDF * neg);
            g_counter = 0;   // reset for next graph replay
        }
    }
}

extern "C" void kernel_launch(void* const* d_in, const int* in_sizes, int n_in,
                              void* d_out, int out_size) {
    const float* z1 = (const float*)d_in[0];
    const float* z2 = (const float*)d_in[1];
    float* out = (float*)d_out;

    softmax_kernel<<<2 * NR, 256>>>(z1, z2);
    pair_kernel<<<NBLK, NT>>>(out);
}

// round 17
// speedup vs baseline: 1.0052x; 1.0052x over previous
#include <cuda_runtime.h>

#define NR 512
#define DD 768
#define EPSF 1e-8f
#define LN2F 0.69314718055994530942f
#define LAMBDF 1.0f

#define TI 16                // pair tile is 16x16
#define BK 64                // k-chunk; 12 chunks; double-buffered smem ~17.4KB
#define BK4 (BK/4)           // 16 float4 per row-chunk
#define PADF 68              // 64 + 4 floats: stride 17 float4 (odd) -> conflict-free LDS.128
#define PAD4 (PADF/4)        // 17
#define NKB (DD/BK)          // 12
#define NBLK ((NR/TI)*(NR/TI))   // 1024 pair blocks
#define NT 128               // 4 warps -> all 4 SMSPs

typedef unsigned long long ull;

// Raw MUFU.LG2/EX2, ftz (exact for our range s in [2e-8, 2]).
__device__ __forceinline__ float flg2(float x) {
    float r;
    asm("lg2.approx.ftz.f32 %0, %1;" : "=f"(r) : "f"(x));
    return r;
}
__device__ __forceinline__ float fex2(float x) {
    float r;
    asm("ex2.approx.ftz.f32 %0, %1;" : "=f"(r) : "f"(x));
    return r;
}
__device__ __forceinline__ void cp16(unsigned dst, const void* src) {
    asm volatile("cp.async.cg.shared.global [%0], [%1], 16;" :: "r"(dst), "l"(src));
}

// Packed f32x2 helpers (Blackwell FFMA2 path — ptxas never auto-emits these).
__device__ __forceinline__ ull pk2(float lo, float hi) {
    ull r;
    asm("mov.b64 %0, {%1, %2};" : "=l"(r) : "f"(lo), "f"(hi));
    return r;
}
__device__ __forceinline__ void upk2(ull v, float& lo, float& hi) {
    asm("mov.b64 {%0, %1}, %2;" : "=f"(lo), "=f"(hi) : "l"(v));
}
__device__ __forceinline__ ull fma2(ull a, ull b, ull c) {
    ull r;
    asm("fma.rn.f32x2 %0, %1, %2, %3;" : "=l"(r) : "l"(a), "l"(b), "l"(c));
    return r;
}

// Packed pair of polynomial log2 on the FMA pipe.
// m = mantissa in [1,2); r = m*(2/3) - 1 in [-1/3, 1/3); exact Taylor deg-8 of
// lg2(1.5*(1+r)) recentered: u = (eb - 126.4150375) + r*q(r). |err| <= 8.1e-6.
__device__ __forceinline__ ull plg2x2(float s0, float s1) {
    int v0 = __float_as_int(s0), v1 = __float_as_int(s1);
    float m0 = __int_as_float((v0 & 0x007FFFFF) | 0x3F800000);
    float m1 = __int_as_float((v1 & 0x007FFFFF) | 0x3F800000);
    float r0 = fmaf(m0, 0.66666669f, -1.0f);
    float r1 = fmaf(m1, 0.66666669f, -1.0f);
    float b0 = (float)(v0 >> 23) - 126.41503750f;   // eb-127+lg2(1.5)
    float b1 = (float)(v1 >> 23) - 126.41503750f;
    ull R = pk2(r0, r1);
    ull q = pk2(-0.18033688f, -0.18033688f);
    q = fma2(q, R, pk2( 0.20609929f,  0.20609929f));
    q = fma2(q, R, pk2(-0.24044917f, -0.24044917f));
    q = fma2(q, R, pk2( 0.28853901f,  0.28853901f));
    q = fma2(q, R, pk2(-0.36067376f, -0.36067376f));
    q = fma2(q, R, pk2( 0.48089835f,  0.48089835f));
    q = fma2(q, R, pk2(-0.72134752f, -0.72134752f));
    q = fma2(q, R, pk2( 1.44269504f,  1.44269504f));
    return fma2(R, q, pk2(b0, b1));
}

// Scratch (no cudaMalloc allowed)
__device__ float    g_P1[NR * DD];   // p1 + eps
__device__ float    g_P2[NR * DD];   // p2 + eps
__device__ float    g_H1[NR];        // sum p1*ln(p1+eps)
__device__ float    g_H2[NR];
__device__ float    g_ptot[NBLK];    // per-block tot partials
__device__ float    g_pdia[NBLK];    // per-block dia partials
__device__ unsigned g_counter = 0;   // ticket for last-block finalize (self-resetting)

// One block per row; blocks [0,512) -> z1, [512,1024) -> z2. 256 threads, 3 elems each.
__global__ void softmax_kernel(const float* __restrict__ z1,
                               const float* __restrict__ z2) {
    const int  row   = blockIdx.x & (NR - 1);
    const bool first = blockIdx.x < NR;
    const float* src = (first ? z1 : z2) + row * DD;
    float*       dst = (first ? g_P1 : g_P2) + row * DD;
    float*      hrow = first ? g_H1 : g_H2;

    const int tid = threadIdx.x;
    const int w = tid >> 5, l = tid & 31;

    float x0 = src[tid];
    float x1 = src[tid + 256];
    float x2 = src[tid + 512];

    __shared__ float sred[8];

    float mx = fmaxf(x0, fmaxf(x1, x2));
    #pragma unroll
    for (int o = 16; o; o >>= 1) mx = fmaxf(mx, __shfl_xor_sync(0xffffffffu, mx, o));
    if (l == 0) sred[w] = mx;
    __syncthreads();
    mx = sred[0];
    #pragma unroll
    for (int i = 1; i < 8; i++) mx = fmaxf(mx, sred[i]);
    __syncthreads();

    const float L2E = 1.4426950408889634f;
    float e0 = fex2((x0 - mx) * L2E);
    float e1 = fex2((x1 - mx) * L2E);
    float e2 = fex2((x2 - mx) * L2E);
    float s = e0 + e1 + e2;
    #pragma unroll
    for (int o = 16; o; o >>= 1) s += __shfl_xor_sync(0xffffffffu, s, o);
    if (l == 0) sred[w] = s;
    __syncthreads();
    s = sred[0];
    #pragma unroll
    for (int i = 1; i < 8; i++) s += sred[i];
    __syncthreads();

    const float inv = 1.0f / s;
    float p0 = e0 * inv, p1 = e1 * inv, p2 = e2 * inv;
    float a0 = p0 + EPSF, a1 = p1 + EPSF, a2 = p2 + EPSF;
    dst[tid]       = a0;
    dst[tid + 256] = a1;
    dst[tid + 512] = a2;

    float h = p0 * flg2(a0) + p1 * flg2(a1) + p2 * flg2(a2);
    #pragma unroll
    for (int o = 16; o; o >>= 1) h += __shfl_xor_sync(0xffffffffu, h, o);
    if (l == 0) sred[w] = h;
    __syncthreads();
    if (tid == 0) {
        float hs = 0.f;
        #pragma unroll
        for (int i = 0; i < 8; i++) hs += sred[i];
        hrow[row] = hs * LN2F;
    }
}

// 16x16 pair tile per block, 128 threads (4 warps), each thread a 2x1 micro-tile.
// cp.async double-buffered k-pipeline. Per k-iter (8 lg2): 6 via MUFU, 2 via a
// PACKED f32x2 polynomial on the FMA pipe (one Horner chain for both) — cuts
// the binding MUFU floor by 25% vs all-MUFU while keeping issue under it.
__global__ void __launch_bounds__(NT, 6) pair_kernel(float* __restrict__ out) {
    __shared__ float As[2][TI * PADF];
    __shared__ float Bs[2][TI * PADF];
    __shared__ float rt4[4], rd4[4];
    __shared__ bool  s_last;

    const int tid = threadIdx.x;
    const int ib = blockIdx.x & 31;   // 512/16 = 32 tiles per dim
    const int jb = blockIdx.x >> 5;
    const int ti = tid & 7;           // i rows: ti, ti+8
    const int tj = tid >> 3;          // j row: tj (0..15)

    const float4* gp1 = (const float4*)(g_P1 + ib * TI * DD);
    const float4* gp2 = (const float4*)(g_P2 + jb * TI * DD);

    // Per-chunk loads: 16x16=256 float4 per matrix, 128 threads -> 2 apiece
    int lrow[2], lcol[2];
    #pragma unroll
    for (int r = 0; r < 2; r++) {
        int idx = tid + r * NT;
        lrow[r] = idx >> 4;     // /16
        lcol[r] = idx & 15;
    }

    #define ISSUE_LOAD(kb, buf)                                                 \
    {                                                                           \
        _Pragma("unroll")                                                       \
        for (int r = 0; r < 2; r++) {                                           \
            int go = lrow[r] * (DD / 4) + (kb) * BK4 + lcol[r];                 \
            unsigned sa = (unsigned)__cvta_generic_to_shared(                   \
                &As[buf][lrow[r] * PADF + lcol[r] * 4]);                        \
            unsigned sb = (unsigned)__cvta_generic_to_shared(                   \
                &Bs[buf][lrow[r] * PADF + lcol[r] * 4]);                        \
            cp16(sa, gp1 + go);                                                 \
            cp16(sb, gp2 + go);                                                 \
        }                                                                       \
        asm volatile("cp.async.commit_group;");                                 \
    }

    // MUFU-path accumulators (row0: x,z -> T1e0, y -> T1o0; row1 likewise)
    float T1e0 = 0.f, T1o0 = 0.f, T1e1 = 0.f, T1o1 = 0.f;
    // Packed poly-path accumulator: lo = row0.w terms, hi = row1.w terms
    ull Tp = pk2(0.0f, 0.0f);

    ISSUE_LOAD(0, 0);

    #pragma unroll 1
    for (int kb = 0; kb < NKB; kb++) {
        const int buf = kb & 1;
        if (kb + 1 < NKB) {
            ISSUE_LOAD(kb + 1, buf ^ 1);
            asm volatile("cp.async.wait_group 1;");
        } else {
            asm volatile("cp.async.wait_group 0;");
        }
        __syncthreads();

        const float4* a0p = (const float4*)(As[buf] + ti * PADF);
        const float4* a1p = (const float4*)(As[buf] + (ti + 8) * PADF);
        const float4* bp  = (const float4*)(Bs[buf] + tj * PADF);

        #pragma unroll
        for (int k = 0; k < BK4; k++) {
            float4 a0 = a0p[k], a1 = a1p[k];
            float4 b  = bp[k];

            // x,y,z of both rows via MUFU (6 lg2)
            {
                float s0 = a0.x + b.x;  float u0 = flg2(s0);
                float s1 = a0.y + b.y;  float u1 = flg2(s1);
                float s2 = a0.z + b.z;  float u2 = flg2(s2);
                T1e0 = fmaf(s0, u0, T1e0);
                T1o0 = fmaf(s1, u1, T1o0);
                T1e0 = fmaf(s2, u2, T1e0);
            }
            {
                float s0 = a1.x + b.x;  float u0 = flg2(s0);
                float s1 = a1.y + b.y;  float u1 = flg2(s1);
                float s2 = a1.z + b.z;  float u2 = flg2(s2);
                T1e1 = fmaf(s0, u0, T1e1);
                T1o1 = fmaf(s1, u1, T1o1);
                T1e1 = fmaf(s2, u2, T1e1);
            }
            // w of both rows via packed FMA-pipe polynomial (2 lg2, 1 chain)
            {
                float s3r0 = a0.w + b.w;
                float s3r1 = a1.w + b.w;
                ull U = plg2x2(s3r0, s3r1);
                Tp = fma2(pk2(s3r0, s3r1), U, Tp);
            }
        }
        __syncthreads();   // orders last reads of buf before it is overwritten
    }
    #undef ISSUE_LOAD

    float Tp0, Tp1;
    upk2(Tp, Tp0, Tp1);

    const int gi0 = ib * TI + ti,  gi1 = gi0 + 8;
    const int gj  = jb * TI + tj;

    const float h10 = g_H1[gi0], h11 = g_H1[gi1];
    const float h2j = g_H2[gj];

    // C ~= ln2*(T1 - 2); jsd = 0.5*(H1 + H2 - C); eps correction is
    // common-mode and cancels in pos-neg (residual ~2e-8 abs).
    #define JSD(T1v, hi, hj) \
        (0.5f * ((hi) + (hj) - LN2F * ((T1v) - 2.0f)))
    float j0 = JSD((T1e0 + T1o0) + Tp0, h10, h2j);
    float j1 = JSD((T1e1 + T1o1) + Tp1, h11, h2j);
    #undef JSD

    float t = j0 + j1;
    float d = 0.f;
    if (gi0 == gj) d += j0;
    if (gi1 == gj) d += j1;

    const int w = tid >> 5, l = tid & 31;
    #pragma unroll
    for (int o = 16; o; o >>= 1) {
        t += __shfl_xor_sync(0xffffffffu, t, o);
        d += __shfl_xor_sync(0xffffffffu, d, o);
    }
    if (l == 0) { rt4[w] = t; rd4[w] = d; }
    __syncthreads();

    if (tid == 0) {
        g_ptot[blockIdx.x] = (rt4[0] + rt4[1]) + (rt4[2] + rt4[3]);
        g_pdia[blockIdx.x] = (rd4[0] + rd4[1]) + (rd4[2] + rd4[3]);
        __threadfence();
        unsigned ticket = atomicAdd(&g_counter, 1u);
        s_last = (ticket == (unsigned)(gridDim.x - 1));
    }
    __syncthreads();

    if (s_last) {
        double dt = 0.0, dd_ = 0.0;
        #pragma unroll
        for (int i = tid; i < NBLK; i += NT) {
            float pt = *(volatile float*)&g_ptot[i];
            float pd = *(volatile float*)&g_pdia[i];
            dt  += (double)pt;
            dd_ += (double)pd;
        }
        #pragma unroll
        for (int o = 16; o; o >>= 1) {
            dt  += __shfl_xor_sync(0xffffffffu, dt, o);
            dd_ += __shfl_xor_sync(0xffffffffu, dd_, o);
        }
        __shared__ double dtot[4], ddia[4];
        if (l == 0) { dtot[w] = dt; ddia[w] = dd_; }
        __syncthreads();
        if (tid == 0) {
            double tot  = (dtot[0] + dtot[1]) + (dtot[2] + dtot[3]);
            double dia_ = (ddia[0] + ddia[1]) + (ddia[2] + ddia[3]);
            double pos = dia_ / (double)NR;
            double neg = -(tot - dia_) / ((double)NR * NR - NR);
            out[0] = (float)(pos + (double)LAMBDF * neg);
            g_counter = 0;   // reset for next graph replay
        }
    }
}

extern "C" void kernel_launch(void* const* d_in, const int* in_sizes, int n_in,
                              void* d_out, int out_size) {
    const float* z1 = (const float*)d_in[0];
    const float* z2 = (const float*)d_in[1];
    float* out = (float*)d_out;

    softmax_kernel<<<2 * NR, 256>>>(z1, z2);
    pair_kernel<<<NBLK, NT>>>(out);
}